// round 3
// baseline (speedup 1.0000x reference)
#include <cuda_runtime.h>
#include <cstdint>
#include <cstddef>

// ---------------------------------------------------------------------------
// Problem constants
// ---------------------------------------------------------------------------
#define N_NODES 100000
#define N_PAD   100096              // 782 * 128  (padded rows for full tiles)
#define N_EDGES 1600000
#define IN_C    128
#define HID     384
#define FC1     128                 // HID/3

// ---------------------------------------------------------------------------
// Scratch (no cudaMalloc allowed)
// ---------------------------------------------------------------------------
__device__ float g_h0[(size_t)N_PAD * IN_C];   // agg + z         [N_PAD,128]
__device__ float g_h1[(size_t)N_PAD * HID];    // selu(h0@W1+b1)  [N_PAD,384]
__device__ float g_h2[(size_t)N_PAD * HID];    // h1@W2+b2        [N_PAD,384]
__device__ float g_h3[(size_t)N_PAD * FC1];    // selu(h2@Wf1+bf1)[N_PAD,128]
__device__ int   g_src[N_EDGES];
__device__ int   g_dst[N_EDGES];
__device__ int   g_is64;                       // 1 if edge_index is int64

// ---------------------------------------------------------------------------
// SELU
// ---------------------------------------------------------------------------
__device__ __forceinline__ float selu_f(float x) {
    const float sc = 1.0507009873554805f;
    const float al = 1.6732632423543772f;
    return x > 0.f ? sc * x : sc * al * (__expf(x) - 1.f);
}

// ---------------------------------------------------------------------------
// K-1: detect edge_index dtype (int64 vs int32), deterministic from data.
// If data is int32, a u64 view packs two edge values; the high word is a
// node id (>0 w.h.p.) so the u64 value is >= 2^32 >> N_NODES.
// ---------------------------------------------------------------------------
__global__ void k_detect(const void* __restrict__ ei) {
    const unsigned long long* p = (const unsigned long long*)ei;
    int ok = 1;
    for (int i = 0; i < 64; i++)
        if (p[i] >= (unsigned long long)N_NODES) { ok = 0; break; }
    g_is64 = ok;
}

// ---------------------------------------------------------------------------
// K-0b: convert edges to int32 with bounds guard (-1 == skip)
// ---------------------------------------------------------------------------
__global__ void k_convert(const void* __restrict__ ei) {
    int e = blockIdx.x * blockDim.x + threadIdx.x;
    if (e >= N_EDGES) return;
    long long s, d;
    if (g_is64) {
        const long long* p = (const long long*)ei;
        s = p[e]; d = p[(size_t)N_EDGES + e];
    } else {
        const int* p = (const int*)ei;
        s = p[e]; d = p[(size_t)N_EDGES + e];
    }
    g_src[e] = ((unsigned long long)s < N_NODES) ? (int)s : -1;
    g_dst[e] = ((unsigned long long)d < N_NODES) ? (int)d : -1;
}

// ---------------------------------------------------------------------------
// K0: h0 = z (rows < N_NODES), 0 for pad rows
// ---------------------------------------------------------------------------
__global__ void k_init(const float* __restrict__ z) {
    int i = blockIdx.x * blockDim.x + threadIdx.x;      // float4 index
    const int TOT = N_PAD * IN_C / 4;
    if (i >= TOT) return;
    float4 v = make_float4(0.f, 0.f, 0.f, 0.f);
    if (i < N_NODES * IN_C / 4) v = ((const float4*)z)[i];
    ((float4*)g_h0)[i] = v;
}

// ---------------------------------------------------------------------------
// K1: scatter-add  h0[dst] += z[src]   (one warp per edge, v4 reductions)
// ---------------------------------------------------------------------------
__global__ void k_scatter(const float* __restrict__ z) {
    int w = (blockIdx.x * blockDim.x + threadIdx.x) >> 5;
    if (w >= N_EDGES) return;
    int lane = threadIdx.x & 31;
    int src = g_src[w];
    int dst = g_dst[w];
    if (src < 0 || dst < 0) return;
    float4 v = *(const float4*)(z + (size_t)src * IN_C + lane * 4);
    float* p = g_h0 + (size_t)dst * IN_C + lane * 4;
    asm volatile("red.global.add.v4.f32 [%0], {%1,%2,%3,%4};"
                 :: "l"(p), "f"(v.x), "f"(v.y), "f"(v.z), "f"(v.w)
                 : "memory");
}

// ---------------------------------------------------------------------------
// K2: fused GEMM + bias (+ optional SELU).  C[M,N] = A[M,K] @ W[K,N] + b
// BM=128, BN=64, BK=16, 256 threads, 8x4 register tile per thread.
// ---------------------------------------------------------------------------
template <bool DO_SELU>
__global__ void __launch_bounds__(256)
k_gemm(const float* __restrict__ A, const float* __restrict__ W,
       const float* __restrict__ bias, float* __restrict__ C,
       int N, int K) {
    __shared__ float As[16][128];   // [k][m]
    __shared__ float Bs[16][64];    // [k][n]

    const int tid  = threadIdx.x;
    const int tcol = tid & 15;      // 0..15  -> N direction (4 cols each)
    const int trow = tid >> 4;      // 0..15  -> M direction (8 rows each)
    const int m0   = blockIdx.y * 128;
    const int n0   = blockIdx.x * 64;

    const float* Ablk = A + (size_t)m0 * K;

    float acc[8][4];
#pragma unroll
    for (int i = 0; i < 8; i++)
#pragma unroll
        for (int j = 0; j < 4; j++) acc[i][j] = 0.f;

    for (int k0 = 0; k0 < K; k0 += 16) {
        // ---- load A tile (128x16) as float4 along K, store transposed
#pragma unroll
        for (int t = 0; t < 2; t++) {
            int idx = tid + t * 256;          // 0..511 float4 slots
            int row = idx >> 2;               // 0..127
            int c4  = idx & 3;                // which float4 in the 16-wide k
            float4 v = *(const float4*)(Ablk + (size_t)row * K + k0 + c4 * 4);
            As[c4 * 4 + 0][row] = v.x;
            As[c4 * 4 + 1][row] = v.y;
            As[c4 * 4 + 2][row] = v.z;
            As[c4 * 4 + 3][row] = v.w;
        }
        // ---- load B tile (16x64), one float4 per thread
        {
            int k  = tid >> 4;                // 0..15
            int c4 = tid & 15;                // 0..15
            *(float4*)&Bs[k][c4 * 4] =
                *(const float4*)(W + (size_t)(k0 + k) * N + n0 + c4 * 4);
        }
        __syncthreads();

#pragma unroll
        for (int k = 0; k < 16; k++) {
            float4 a0 = *(const float4*)&As[k][trow * 8];
            float4 a1 = *(const float4*)&As[k][trow * 8 + 4];
            float4 b  = *(const float4*)&Bs[k][tcol * 4];
            float a[8] = {a0.x, a0.y, a0.z, a0.w, a1.x, a1.y, a1.z, a1.w};
            float bb[4] = {b.x, b.y, b.z, b.w};
#pragma unroll
            for (int i = 0; i < 8; i++)
#pragma unroll
                for (int j = 0; j < 4; j++)
                    acc[i][j] = fmaf(a[i], bb[j], acc[i][j]);
        }
        __syncthreads();
    }

    // ---- epilogue: bias (+ selu), float4 stores
    float4 bv = *(const float4*)(bias + n0 + tcol * 4);
    float bias4[4] = {bv.x, bv.y, bv.z, bv.w};
#pragma unroll
    for (int i = 0; i < 8; i++) {
        int row = m0 + trow * 8 + i;
        float4 o;
        float v0 = acc[i][0] + bias4[0];
        float v1 = acc[i][1] + bias4[1];
        float v2 = acc[i][2] + bias4[2];
        float v3 = acc[i][3] + bias4[3];
        if (DO_SELU) {
            v0 = selu_f(v0); v1 = selu_f(v1); v2 = selu_f(v2); v3 = selu_f(v3);
        }
        o.x = v0; o.y = v1; o.z = v2; o.w = v3;
        *(float4*)(C + (size_t)row * N + n0 + tcol * 4) = o;
    }
}

// ---------------------------------------------------------------------------
// K3: final head  out[n] = h3[n,:] . Wf2 + bf2   (one warp per row)
// ---------------------------------------------------------------------------
__global__ void k_out(const float* __restrict__ Wf2,
                      const float* __restrict__ bf2,
                      float* __restrict__ out) {
    int w = (blockIdx.x * blockDim.x + threadIdx.x) >> 5;
    if (w >= N_NODES) return;
    int lane = threadIdx.x & 31;
    float4 h  = *(const float4*)(g_h3 + (size_t)w * FC1 + lane * 4);
    float4 wt = *(const float4*)(Wf2 + lane * 4);
    float s = h.x * wt.x + h.y * wt.y + h.z * wt.z + h.w * wt.w;
#pragma unroll
    for (int off = 16; off; off >>= 1) s += __shfl_xor_sync(0xffffffffu, s, off);
    if (lane == 0) out[w] = s + bf2[0];
}

// ---------------------------------------------------------------------------
// Launch. Inputs identified BY ELEMENT COUNT (robust to harness ordering):
//   12800000 -> z            3200000 -> edge_index     100000 -> batch
//   147456   -> W2           49152   -> W1 then Wf1    384 -> b1 then b2
//   128      -> bf1 then Wf2 1       -> bf2
// ---------------------------------------------------------------------------
extern "C" void kernel_launch(void* const* d_in, const int* in_sizes, int n_in,
                              void* d_out, int out_size) {
    const float* z  = nullptr;
    const float* W1 = nullptr, *b1 = nullptr, *W2 = nullptr, *b2 = nullptr;
    const float* Wf1 = nullptr, *bf1 = nullptr, *Wf2 = nullptr, *bf2 = nullptr;
    const void*  ei = nullptr;

    int n49152 = 0, n384 = 0, n128 = 0;
    for (int i = 0; i < n_in; i++) {
        int s = in_sizes[i];
        const void* p = d_in[i];
        switch (s) {
            case 12800000: z  = (const float*)p; break;
            case 3200000:  ei = p;               break;
            case 100000:   /* batch, unused */   break;
            case 147456:   W2 = (const float*)p; break;
            case 49152:
                if (n49152++ == 0) W1 = (const float*)p; else Wf1 = (const float*)p;
                break;
            case 384:
                if (n384++ == 0) b1 = (const float*)p; else b2 = (const float*)p;
                break;
            case 128:
                if (n128++ == 0) bf1 = (const float*)p; else Wf2 = (const float*)p;
                break;
            case 1:        bf2 = (const float*)p; break;
            default: break;
        }
    }
    float* out = (float*)d_out;

    float *h0, *h1, *h2, *h3;
    cudaGetSymbolAddress((void**)&h0, g_h0);
    cudaGetSymbolAddress((void**)&h1, g_h1);
    cudaGetSymbolAddress((void**)&h2, g_h2);
    cudaGetSymbolAddress((void**)&h3, g_h3);

    // edge preprocessing: dtype detect + int32 conversion (guarded)
    k_detect<<<1, 1>>>(ei);
    k_convert<<<(N_EDGES + 255) / 256, 256>>>(ei);

    // K0: init h0 = z (+ zero pad rows)
    {
        int tot = N_PAD * IN_C / 4;
        k_init<<<(tot + 255) / 256, 256>>>(z);
    }
    // K1: scatter-add (1 warp / edge, 8 edges / block)
    k_scatter<<<N_EDGES / 8, 256>>>(z);

    // K2a: h1 = selu(h0 @ W1 + b1)           [N_PAD,128]x[128,384]
    k_gemm<true ><<<dim3(HID / 64, N_PAD / 128), 256>>>(h0, W1, b1, h1, HID, IN_C);
    // K2b: h2 = h1 @ W2 + b2                 [N_PAD,384]x[384,384]
    k_gemm<false><<<dim3(HID / 64, N_PAD / 128), 256>>>(h1, W2, b2, h2, HID, HID);
    // K2c: h3 = selu(h2 @ Wf1 + bf1)         [N_PAD,384]x[384,128]
    k_gemm<true ><<<dim3(FC1 / 64, N_PAD / 128), 256>>>(h2, Wf1, bf1, h3, FC1, HID);

    // K3: out = h3 @ Wf2 + bf2               [N,128]x[128,1]
    k_out<<<(N_NODES * 32 + 255) / 256, 256>>>(Wf2, bf2, out);
}

// round 5
// speedup vs baseline: 1.4300x; 1.4300x over previous
#include <cuda_runtime.h>
#include <cuda_bf16.h>
#include <cstdint>
#include <cstddef>

// ---------------------------------------------------------------------------
// Problem constants
// ---------------------------------------------------------------------------
#define N_NODES 100000
#define N_PAD   100096              // 782 * 128
#define N_EDGES 1600000
#define IN_C    128
#define HID     384
#define FC1     128

// ---------------------------------------------------------------------------
// Scratch (no cudaMalloc allowed)
// ---------------------------------------------------------------------------
__device__ float g_h0[(size_t)N_PAD * IN_C];
__device__ float g_h1[(size_t)N_PAD * HID];
__device__ float g_h2[(size_t)N_PAD * HID];
__device__ float g_h3[(size_t)N_PAD * FC1];
__device__ int   g_src[N_EDGES];
__device__ int   g_dst[N_EDGES];
__device__ int   g_is64;

// ---------------------------------------------------------------------------
__device__ __forceinline__ float selu_f(float x) {
    const float sc = 1.0507009873554805f;
    const float al = 1.6732632423543772f;
    return x > 0.f ? sc * x : sc * al * (__expf(x) - 1.f);
}

__device__ __forceinline__ uint32_t s2u(const void* p) {
    return (uint32_t)__cvta_generic_to_shared(p);
}

// ldmatrix x4 (A fragments, row-major)
__device__ __forceinline__ void ldm_x4(uint32_t r[4], uint32_t addr) {
    asm volatile("ldmatrix.sync.aligned.m8n8.x4.shared.b16 {%0,%1,%2,%3}, [%4];"
                 : "=r"(r[0]), "=r"(r[1]), "=r"(r[2]), "=r"(r[3]) : "r"(addr));
}
// ldmatrix x4 transposed (B fragments from [k][n] tile)
__device__ __forceinline__ void ldm_x4_t(uint32_t r[4], uint32_t addr) {
    asm volatile("ldmatrix.sync.aligned.m8n8.x4.trans.shared.b16 {%0,%1,%2,%3}, [%4];"
                 : "=r"(r[0]), "=r"(r[1]), "=r"(r[2]), "=r"(r[3]) : "r"(addr));
}
// mma m16n8k16 bf16 -> f32 accumulate
__device__ __forceinline__ void mma_bf16(float c[4], const uint32_t a[4],
                                         const uint32_t b0, const uint32_t b1) {
    asm volatile(
        "mma.sync.aligned.m16n8k16.row.col.f32.bf16.bf16.f32 "
        "{%0,%1,%2,%3}, {%4,%5,%6,%7}, {%8,%9}, {%0,%1,%2,%3};"
        : "+f"(c[0]), "+f"(c[1]), "+f"(c[2]), "+f"(c[3])
        : "r"(a[0]), "r"(a[1]), "r"(a[2]), "r"(a[3]), "r"(b0), "r"(b1));
}

// ---------------------------------------------------------------------------
// edge dtype detect / convert (unchanged, proven)
// ---------------------------------------------------------------------------
__global__ void k_detect(const void* __restrict__ ei) {
    const unsigned long long* p = (const unsigned long long*)ei;
    int ok = 1;
    for (int i = 0; i < 64; i++)
        if (p[i] >= (unsigned long long)N_NODES) { ok = 0; break; }
    g_is64 = ok;
}

__global__ void k_convert(const void* __restrict__ ei) {
    int e = blockIdx.x * blockDim.x + threadIdx.x;
    if (e >= N_EDGES) return;
    long long s, d;
    if (g_is64) {
        const long long* p = (const long long*)ei;
        s = p[e]; d = p[(size_t)N_EDGES + e];
    } else {
        const int* p = (const int*)ei;
        s = p[e]; d = p[(size_t)N_EDGES + e];
    }
    g_src[e] = ((unsigned long long)s < N_NODES) ? (int)s : -1;
    g_dst[e] = ((unsigned long long)d < N_NODES) ? (int)d : -1;
}

__global__ void k_init(const float* __restrict__ z) {
    int i = blockIdx.x * blockDim.x + threadIdx.x;
    const int TOT = N_PAD * IN_C / 4;
    if (i >= TOT) return;
    float4 v = make_float4(0.f, 0.f, 0.f, 0.f);
    if (i < N_NODES * IN_C / 4) v = ((const float4*)z)[i];
    ((float4*)g_h0)[i] = v;
}

__global__ void k_scatter(const float* __restrict__ z) {
    int w = (blockIdx.x * blockDim.x + threadIdx.x) >> 5;
    if (w >= N_EDGES) return;
    int lane = threadIdx.x & 31;
    int src = g_src[w];
    int dst = g_dst[w];
    if (src < 0 || dst < 0) return;
    float4 v = *(const float4*)(z + (size_t)src * IN_C + lane * 4);
    float* p = g_h0 + (size_t)dst * IN_C + lane * 4;
    asm volatile("red.global.add.v4.f32 [%0], {%1,%2,%3,%4};"
                 :: "l"(p), "f"(v.x), "f"(v.y), "f"(v.z), "f"(v.w)
                 : "memory");
}

// ---------------------------------------------------------------------------
// Tensor-core GEMM, bf16x3 split.  C[M,N] = A[M,K] @ W[K,N] + bias (+SELU)
// BM=128, BN=64, BK=32. 256 threads = 8 warps in 4(m) x 2(n); warp tile 32x32.
// Smem strides padded for conflict-free ldmatrix: A 40 bf16/row, B 72 bf16/row.
// ---------------------------------------------------------------------------
#define LDA 40
#define LDB 72

template <bool DO_SELU>
__global__ void __launch_bounds__(256, 1)
k_gemm_mma(const float* __restrict__ A, const float* __restrict__ W,
           const float* __restrict__ bias, float* __restrict__ C,
           int N, int K) {
    __shared__ __nv_bfloat16 sAh[128 * LDA];
    __shared__ __nv_bfloat16 sAl[128 * LDA];
    __shared__ __nv_bfloat16 sBh[32 * LDB];
    __shared__ __nv_bfloat16 sBl[32 * LDB];

    const int tid  = threadIdx.x;
    const int lane = tid & 31;
    const int wid  = tid >> 5;
    const int wm   = (wid & 3) * 32;      // warp row offset in block tile
    const int wn   = (wid >> 2) * 32;     // warp col offset in block tile
    const int m0   = blockIdx.y * 128;
    const int n0   = blockIdx.x * 64;

    float c[2][4][4];
#pragma unroll
    for (int i = 0; i < 2; i++)
#pragma unroll
        for (int j = 0; j < 4; j++)
#pragma unroll
            for (int k = 0; k < 4; k++) c[i][j][k] = 0.f;

    for (int k0 = 0; k0 < K; k0 += 32) {
        // ---- load + split A tile: 128 x 32 floats
#pragma unroll
        for (int t = 0; t < 4; t++) {
            int idx = tid + t * 256;          // 0..1023 float4 slots
            int row = idx >> 3;               // 0..127
            int seg = idx & 7;                // float4 within 32-wide k
            float4 v = *(const float4*)(A + (size_t)(m0 + row) * K + k0 + seg * 4);
            float xs[4] = {v.x, v.y, v.z, v.w};
            int o = row * LDA + seg * 4;
#pragma unroll
            for (int j = 0; j < 4; j++) {
                __nv_bfloat16 h = __float2bfloat16(xs[j]);
                sAh[o + j] = h;
                sAl[o + j] = __float2bfloat16(xs[j] - __bfloat162float(h));
            }
        }
        // ---- load + split B tile: 32 x 64 floats
#pragma unroll
        for (int t = 0; t < 2; t++) {
            int idx = tid + t * 256;          // 0..511 float4 slots
            int row = idx >> 4;               // 0..31 (k)
            int seg = idx & 15;               // float4 within 64-wide n
            float4 v = *(const float4*)(W + (size_t)(k0 + row) * N + n0 + seg * 4);
            float xs[4] = {v.x, v.y, v.z, v.w};
            int o = row * LDB + seg * 4;
#pragma unroll
            for (int j = 0; j < 4; j++) {
                __nv_bfloat16 h = __float2bfloat16(xs[j]);
                sBh[o + j] = h;
                sBl[o + j] = __float2bfloat16(xs[j] - __bfloat162float(h));
            }
        }
        __syncthreads();

#pragma unroll
        for (int kk = 0; kk < 2; kk++) {      // two k16 steps
            uint32_t ah[2][4], al[2][4];
#pragma unroll
            for (int mt = 0; mt < 2; mt++) {
                int row  = wm + mt * 16 + (lane & 15);
                int kofs = kk * 16 + (lane >> 4) * 8;
                ldm_x4(ah[mt], s2u(&sAh[row * LDA + kofs]));
                ldm_x4(al[mt], s2u(&sAl[row * LDA + kofs]));
            }
#pragma unroll
            for (int ng = 0; ng < 2; ng++) {  // two n16 groups
                uint32_t bh[4], bl[4];
                int krow = kk * 16 + (lane & 15);
                int ncol = wn + ng * 16 + (lane >> 4) * 8;
                ldm_x4_t(bh, s2u(&sBh[krow * LDB + ncol]));
                ldm_x4_t(bl, s2u(&sBl[krow * LDB + ncol]));
#pragma unroll
                for (int mt = 0; mt < 2; mt++) {
#pragma unroll
                    for (int nn = 0; nn < 2; nn++) {
                        float* cc = c[mt][ng * 2 + nn];
                        mma_bf16(cc, ah[mt], bh[nn * 2], bh[nn * 2 + 1]);  // hi*hi
                        mma_bf16(cc, ah[mt], bl[nn * 2], bl[nn * 2 + 1]);  // hi*lo
                        mma_bf16(cc, al[mt], bh[nn * 2], bh[nn * 2 + 1]);  // lo*hi
                    }
                }
            }
        }
        __syncthreads();
    }

    // ---- epilogue: bias (+SELU), direct global stores
    const int rbase = m0 + wm + (lane >> 2);
    const int cbase = n0 + wn + (lane & 3) * 2;
#pragma unroll
    for (int mt = 0; mt < 2; mt++) {
#pragma unroll
        for (int nt = 0; nt < 4; nt++) {
            int row = rbase + mt * 16;
            int col = cbase + nt * 8;
            float b0 = bias[col], b1 = bias[col + 1];
            float v0 = c[mt][nt][0] + b0, v1 = c[mt][nt][1] + b1;
            float v2 = c[mt][nt][2] + b0, v3 = c[mt][nt][3] + b1;
            if (DO_SELU) {
                v0 = selu_f(v0); v1 = selu_f(v1);
                v2 = selu_f(v2); v3 = selu_f(v3);
            }
            float2 p0 = make_float2(v0, v1);
            float2 p1 = make_float2(v2, v3);
            *(float2*)(C + (size_t)row * N + col) = p0;
            *(float2*)(C + (size_t)(row + 8) * N + col) = p1;
        }
    }
}

// ---------------------------------------------------------------------------
// K3: final head
// ---------------------------------------------------------------------------
__global__ void k_out(const float* __restrict__ Wf2,
                      const float* __restrict__ bf2,
                      float* __restrict__ out) {
    int w = (blockIdx.x * blockDim.x + threadIdx.x) >> 5;
    if (w >= N_NODES) return;
    int lane = threadIdx.x & 31;
    float4 h  = *(const float4*)(g_h3 + (size_t)w * FC1 + lane * 4);
    float4 wt = *(const float4*)(Wf2 + lane * 4);
    float s = h.x * wt.x + h.y * wt.y + h.z * wt.z + h.w * wt.w;
#pragma unroll
    for (int off = 16; off; off >>= 1) s += __shfl_xor_sync(0xffffffffu, s, off);
    if (lane == 0) out[w] = s + bf2[0];
}

// ---------------------------------------------------------------------------
// Launch. Inputs identified by element count (proven in R3).
// ---------------------------------------------------------------------------
extern "C" void kernel_launch(void* const* d_in, const int* in_sizes, int n_in,
                              void* d_out, int out_size) {
    const float* z  = nullptr;
    const float* W1 = nullptr, *b1 = nullptr, *W2 = nullptr, *b2 = nullptr;
    const float* Wf1 = nullptr, *bf1 = nullptr, *Wf2 = nullptr, *bf2 = nullptr;
    const void*  ei = nullptr;

    int n49152 = 0, n384 = 0, n128 = 0;
    for (int i = 0; i < n_in; i++) {
        int s = in_sizes[i];
        const void* p = d_in[i];
        switch (s) {
            case 12800000: z  = (const float*)p; break;
            case 3200000:  ei = p;               break;
            case 100000:   break;
            case 147456:   W2 = (const float*)p; break;
            case 49152:
                if (n49152++ == 0) W1 = (const float*)p; else Wf1 = (const float*)p;
                break;
            case 384:
                if (n384++ == 0) b1 = (const float*)p; else b2 = (const float*)p;
                break;
            case 128:
                if (n128++ == 0) bf1 = (const float*)p; else Wf2 = (const float*)p;
                break;
            case 1:        bf2 = (const float*)p; break;
            default: break;
        }
    }
    float* out = (float*)d_out;

    float *h0, *h1, *h2, *h3;
    cudaGetSymbolAddress((void**)&h0, g_h0);
    cudaGetSymbolAddress((void**)&h1, g_h1);
    cudaGetSymbolAddress((void**)&h2, g_h2);
    cudaGetSymbolAddress((void**)&h3, g_h3);

    k_detect<<<1, 1>>>(ei);
    k_convert<<<(N_EDGES + 255) / 256, 256>>>(ei);

    {
        int tot = N_PAD * IN_C / 4;
        k_init<<<(tot + 255) / 256, 256>>>(z);
    }
    k_scatter<<<N_EDGES / 8, 256>>>(z);

    // h1 = selu(h0 @ W1 + b1)           [N_PAD,128] x [128,384]
    k_gemm_mma<true ><<<dim3(HID / 64, N_PAD / 128), 256>>>(h0, W1, b1, h1, HID, IN_C);
    // h2 = h1 @ W2 + b2                 [N_PAD,384] x [384,384]
    k_gemm_mma<false><<<dim3(HID / 64, N_PAD / 128), 256>>>(h1, W2, b2, h2, HID, HID);
    // h3 = selu(h2 @ Wf1 + bf1)         [N_PAD,384] x [384,128]
    k_gemm_mma<true ><<<dim3(FC1 / 64, N_PAD / 128), 256>>>(h2, Wf1, bf1, h3, FC1, HID);

    // out = h3 @ Wf2 + bf2
    k_out<<<(N_NODES * 32 + 255) / 256, 256>>>(Wf2, bf2, out);
}

// round 6
// speedup vs baseline: 1.7654x; 1.2346x over previous
#include <cuda_runtime.h>
#include <cuda_bf16.h>
#include <cstdint>
#include <cstddef>

// ---------------------------------------------------------------------------
// Problem constants
// ---------------------------------------------------------------------------
#define N_NODES 100000
#define N_PAD   100096              // 782 * 128
#define N_EDGES 1600000
#define IN_C    128
#define HID     384
#define FC1     128

typedef __nv_bfloat16 bf16;

// ---------------------------------------------------------------------------
// Scratch (no cudaMalloc allowed)
// ---------------------------------------------------------------------------
__device__ float g_h0 [(size_t)N_PAD * IN_C];
__device__ bf16  g_h0h[(size_t)N_PAD * IN_C];
__device__ bf16  g_h0l[(size_t)N_PAD * IN_C];
__device__ bf16  g_h1h[(size_t)N_PAD * HID];
__device__ bf16  g_h1l[(size_t)N_PAD * HID];
__device__ bf16  g_h2h[(size_t)N_PAD * HID];
__device__ bf16  g_h2l[(size_t)N_PAD * HID];
__device__ float g_h3 [(size_t)N_PAD * FC1];
__device__ bf16  g_W1h[IN_C * HID],  g_W1l[IN_C * HID];
__device__ bf16  g_W2h[HID * HID],   g_W2l[HID * HID];
__device__ bf16  g_Wfh[HID * FC1],   g_Wfl[HID * FC1];
__device__ int   g_src[N_EDGES];
__device__ int   g_dst[N_EDGES];
__device__ int   g_is64;

// ---------------------------------------------------------------------------
__device__ __forceinline__ float selu_f(float x) {
    const float sc = 1.0507009873554805f;
    const float al = 1.6732632423543772f;
    return x > 0.f ? sc * x : sc * al * (__expf(x) - 1.f);
}

__device__ __forceinline__ uint32_t s2u(const void* p) {
    return (uint32_t)__cvta_generic_to_shared(p);
}
__device__ __forceinline__ void cp16(void* smem_dst, const void* gmem_src) {
    asm volatile("cp.async.cg.shared.global [%0], [%1], 16;"
                 :: "r"(s2u(smem_dst)), "l"(gmem_src));
}
__device__ __forceinline__ void ldm_x4(uint32_t r[4], uint32_t addr) {
    asm volatile("ldmatrix.sync.aligned.m8n8.x4.shared.b16 {%0,%1,%2,%3}, [%4];"
                 : "=r"(r[0]), "=r"(r[1]), "=r"(r[2]), "=r"(r[3]) : "r"(addr));
}
__device__ __forceinline__ void ldm_x4_t(uint32_t r[4], uint32_t addr) {
    asm volatile("ldmatrix.sync.aligned.m8n8.x4.trans.shared.b16 {%0,%1,%2,%3}, [%4];"
                 : "=r"(r[0]), "=r"(r[1]), "=r"(r[2]), "=r"(r[3]) : "r"(addr));
}
__device__ __forceinline__ void mma_bf16(float c[4], const uint32_t a[4],
                                         const uint32_t b0, const uint32_t b1) {
    asm volatile(
        "mma.sync.aligned.m16n8k16.row.col.f32.bf16.bf16.f32 "
        "{%0,%1,%2,%3}, {%4,%5,%6,%7}, {%8,%9}, {%0,%1,%2,%3};"
        : "+f"(c[0]), "+f"(c[1]), "+f"(c[2]), "+f"(c[3])
        : "r"(a[0]), "r"(a[1]), "r"(a[2]), "r"(a[3]), "r"(b0), "r"(b1));
}

// ---------------------------------------------------------------------------
// edge dtype detect / convert (proven)
// ---------------------------------------------------------------------------
__global__ void k_detect(const void* __restrict__ ei) {
    const unsigned long long* p = (const unsigned long long*)ei;
    int ok = 1;
    for (int i = 0; i < 64; i++)
        if (p[i] >= (unsigned long long)N_NODES) { ok = 0; break; }
    g_is64 = ok;
}

__global__ void k_convert(const void* __restrict__ ei) {
    int e = blockIdx.x * blockDim.x + threadIdx.x;
    if (e >= N_EDGES) return;
    long long s, d;
    if (g_is64) {
        const long long* p = (const long long*)ei;
        s = p[e]; d = p[(size_t)N_EDGES + e];
    } else {
        const int* p = (const int*)ei;
        s = p[e]; d = p[(size_t)N_EDGES + e];
    }
    g_src[e] = ((unsigned long long)s < N_NODES) ? (int)s : -1;
    g_dst[e] = ((unsigned long long)d < N_NODES) ? (int)d : -1;
}

__global__ void k_init(const float* __restrict__ z) {
    int i = blockIdx.x * blockDim.x + threadIdx.x;
    const int TOT = N_PAD * IN_C / 4;
    if (i >= TOT) return;
    float4 v = make_float4(0.f, 0.f, 0.f, 0.f);
    if (i < N_NODES * IN_C / 4) v = ((const float4*)z)[i];
    ((float4*)g_h0)[i] = v;
}

__global__ void k_scatter(const float* __restrict__ z) {
    int w = (blockIdx.x * blockDim.x + threadIdx.x) >> 5;
    if (w >= N_EDGES) return;
    int lane = threadIdx.x & 31;
    int src = g_src[w];
    int dst = g_dst[w];
    if (src < 0 || dst < 0) return;
    float4 v = *(const float4*)(z + (size_t)src * IN_C + lane * 4);
    float* p = g_h0 + (size_t)dst * IN_C + lane * 4;
    asm volatile("red.global.add.v4.f32 [%0], {%1,%2,%3,%4};"
                 :: "l"(p), "f"(v.x), "f"(v.y), "f"(v.z), "f"(v.w)
                 : "memory");
}

// ---------------------------------------------------------------------------
// split fp32 -> (hi, lo) bf16 planes, elementwise (n divisible by 4)
// ---------------------------------------------------------------------------
__global__ void k_split(const float* __restrict__ X, bf16* __restrict__ Xh,
                        bf16* __restrict__ Xl, int n4) {
    int i = blockIdx.x * blockDim.x + threadIdx.x;
    if (i >= n4) return;
    float4 v = ((const float4*)X)[i];
    float xs[4] = {v.x, v.y, v.z, v.w};
    bf16 h[4], l[4];
#pragma unroll
    for (int j = 0; j < 4; j++) {
        h[j] = __float2bfloat16(xs[j]);
        l[j] = __float2bfloat16(xs[j] - __bfloat162float(h[j]));
    }
    ((__nv_bfloat162*)Xh)[i * 2]     = __nv_bfloat162(h[0], h[1]);
    ((__nv_bfloat162*)Xh)[i * 2 + 1] = __nv_bfloat162(h[2], h[3]);
    ((__nv_bfloat162*)Xl)[i * 2]     = __nv_bfloat162(l[0], l[1]);
    ((__nv_bfloat162*)Xl)[i * 2 + 1] = __nv_bfloat162(l[2], l[3]);
}

// ---------------------------------------------------------------------------
// Pipelined tensor-core GEMM on pre-split bf16 planes.
// C[M,N] = A[M,K] @ W[K,N] + bias (+SELU); A,W given as hi/lo planes.
// BM=128, BN=64, BK=32; 256 thr = 8 warps (4m x 2n), warp tile 32x32.
// 2-stage cp.async pipeline, dynamic smem (59.4 KB).
// Padded smem rows: A stride 40 bf16 (80B), B stride 72 bf16 (144B).
// ---------------------------------------------------------------------------
#define LDA 40
#define LDB 72
#define OFF_AH 0
#define OFF_AL (128 * LDA)                  // 5120
#define OFF_BH (2 * 128 * LDA)              // 10240
#define OFF_BL (2 * 128 * LDA + 32 * LDB)   // 12544
#define STAGE  (2 * 128 * LDA + 2 * 32 * LDB)  // 14848 elems
#define SMEM_BYTES (2 * STAGE * 2)          // 59392 B

template <bool DO_SELU, bool OUT_SPLIT>
__global__ void __launch_bounds__(256, 1)
k_gemm2(const bf16* __restrict__ Ah, const bf16* __restrict__ Al,
        const bf16* __restrict__ Bh, const bf16* __restrict__ Bl,
        const float* __restrict__ bias,
        float* __restrict__ C, bf16* __restrict__ Ch, bf16* __restrict__ Cl,
        int N, int K) {
    extern __shared__ bf16 sm[];

    const int tid  = threadIdx.x;
    const int lane = tid & 31;
    const int wid  = tid >> 5;
    const int wm   = (wid & 3) * 32;
    const int wn   = (wid >> 2) * 32;
    const int m0   = blockIdx.y * 128;
    const int n0   = blockIdx.x * 64;
    const int NIT  = K / 32;

    // ---- async tile loader: stage buf <- k-slice it
    auto load_stage = [&](int it, int buf) {
        bf16* base = sm + buf * STAGE;
        const int k0 = it * 32;
        // A planes: 128x32 bf16 = 512 chunks of 16B each plane
#pragma unroll
        for (int t = 0; t < 2; t++) {
            int c = tid + t * 256;
            int row = c >> 2, seg = c & 3;
            size_t g = (size_t)(m0 + row) * K + k0 + seg * 8;
            int    s = row * LDA + seg * 8;
            cp16(base + OFF_AH + s, Ah + g);
            cp16(base + OFF_AL + s, Al + g);
        }
        // B planes: 32x64 bf16 = 256 chunks each plane
        {
            int row = tid >> 3, seg = tid & 7;
            size_t g = (size_t)(k0 + row) * N + n0 + seg * 8;
            int    s = row * LDB + seg * 8;
            cp16(base + OFF_BH + s, Bh + g);
            cp16(base + OFF_BL + s, Bl + g);
        }
        asm volatile("cp.async.commit_group;");
    };

    float acc[2][4][4];
#pragma unroll
    for (int i = 0; i < 2; i++)
#pragma unroll
        for (int j = 0; j < 4; j++)
#pragma unroll
            for (int k = 0; k < 4; k++) acc[i][j][k] = 0.f;

    load_stage(0, 0);

    for (int it = 0; it < NIT; it++) {
        if (it + 1 < NIT) {
            load_stage(it + 1, (it + 1) & 1);
            asm volatile("cp.async.wait_group 1;");
        } else {
            asm volatile("cp.async.wait_group 0;");
        }
        __syncthreads();

        bf16* base = sm + (it & 1) * STAGE;
        bf16* pAh = base + OFF_AH;
        bf16* pAl = base + OFF_AL;
        bf16* pBh = base + OFF_BH;
        bf16* pBl = base + OFF_BL;

#pragma unroll
        for (int kk = 0; kk < 2; kk++) {
            uint32_t ah[2][4], al[2][4];
#pragma unroll
            for (int mt = 0; mt < 2; mt++) {
                int row  = wm + mt * 16 + (lane & 15);
                int kofs = kk * 16 + (lane >> 4) * 8;
                ldm_x4(ah[mt], s2u(pAh + row * LDA + kofs));
                ldm_x4(al[mt], s2u(pAl + row * LDA + kofs));
            }
#pragma unroll
            for (int ng = 0; ng < 2; ng++) {
                uint32_t bh[4], bl[4];
                int krow = kk * 16 + (lane & 15);
                int ncol = wn + ng * 16 + (lane >> 4) * 8;
                ldm_x4_t(bh, s2u(pBh + krow * LDB + ncol));
                ldm_x4_t(bl, s2u(pBl + krow * LDB + ncol));
#pragma unroll
                for (int mt = 0; mt < 2; mt++) {
#pragma unroll
                    for (int nn = 0; nn < 2; nn++) {
                        float* cc = acc[mt][ng * 2 + nn];
                        mma_bf16(cc, ah[mt], bh[nn * 2], bh[nn * 2 + 1]);
                        mma_bf16(cc, ah[mt], bl[nn * 2], bl[nn * 2 + 1]);
                        mma_bf16(cc, al[mt], bh[nn * 2], bh[nn * 2 + 1]);
                    }
                }
            }
        }
        __syncthreads();
    }

    // ---- epilogue
    const int rbase = m0 + wm + (lane >> 2);
    const int cbase = n0 + wn + (lane & 3) * 2;
#pragma unroll
    for (int mt = 0; mt < 2; mt++) {
#pragma unroll
        for (int nt = 0; nt < 4; nt++) {
            int row = rbase + mt * 16;
            int col = cbase + nt * 8;
            float b0 = bias[col], b1 = bias[col + 1];
            float v[2][2] = {{acc[mt][nt][0] + b0, acc[mt][nt][1] + b1},
                             {acc[mt][nt][2] + b0, acc[mt][nt][3] + b1}};
#pragma unroll
            for (int r = 0; r < 2; r++) {
                if (DO_SELU) { v[r][0] = selu_f(v[r][0]); v[r][1] = selu_f(v[r][1]); }
                size_t o = (size_t)(row + r * 8) * N + col;
                if (OUT_SPLIT) {
                    bf16 h0 = __float2bfloat16(v[r][0]);
                    bf16 h1 = __float2bfloat16(v[r][1]);
                    bf16 l0 = __float2bfloat16(v[r][0] - __bfloat162float(h0));
                    bf16 l1 = __float2bfloat16(v[r][1] - __bfloat162float(h1));
                    *(__nv_bfloat162*)(Ch + o) = __nv_bfloat162(h0, h1);
                    *(__nv_bfloat162*)(Cl + o) = __nv_bfloat162(l0, l1);
                } else {
                    *(float2*)(C + o) = make_float2(v[r][0], v[r][1]);
                }
            }
        }
    }
}

// ---------------------------------------------------------------------------
// final head
// ---------------------------------------------------------------------------
__global__ void k_out(const float* __restrict__ Wf2,
                      const float* __restrict__ bf2,
                      float* __restrict__ out) {
    int w = (blockIdx.x * blockDim.x + threadIdx.x) >> 5;
    if (w >= N_NODES) return;
    int lane = threadIdx.x & 31;
    float4 h  = *(const float4*)(g_h3 + (size_t)w * FC1 + lane * 4);
    float4 wt = *(const float4*)(Wf2 + lane * 4);
    float s = h.x * wt.x + h.y * wt.y + h.z * wt.z + h.w * wt.w;
#pragma unroll
    for (int off = 16; off; off >>= 1) s += __shfl_xor_sync(0xffffffffu, s, off);
    if (lane == 0) out[w] = s + bf2[0];
}

// ---------------------------------------------------------------------------
// Launch
// ---------------------------------------------------------------------------
extern "C" void kernel_launch(void* const* d_in, const int* in_sizes, int n_in,
                              void* d_out, int out_size) {
    const float* z  = nullptr;
    const float* W1 = nullptr, *b1 = nullptr, *W2 = nullptr, *b2 = nullptr;
    const float* Wf1 = nullptr, *bf1 = nullptr, *Wf2 = nullptr, *bf2 = nullptr;
    const void*  ei = nullptr;

    int n49152 = 0, n384 = 0, n128 = 0;
    for (int i = 0; i < n_in; i++) {
        int s = in_sizes[i];
        const void* p = d_in[i];
        switch (s) {
            case 12800000: z  = (const float*)p; break;
            case 3200000:  ei = p;               break;
            case 100000:   break;
            case 147456:   W2 = (const float*)p; break;
            case 49152:
                if (n49152++ == 0) W1 = (const float*)p; else Wf1 = (const float*)p;
                break;
            case 384:
                if (n384++ == 0) b1 = (const float*)p; else b2 = (const float*)p;
                break;
            case 128:
                if (n128++ == 0) bf1 = (const float*)p; else Wf2 = (const float*)p;
                break;
            case 1:        bf2 = (const float*)p; break;
            default: break;
        }
    }
    float* out = (float*)d_out;

    float *h0, *h3;
    bf16 *h0h, *h0l, *h1h, *h1l, *h2h, *h2l;
    bf16 *W1h, *W1l, *W2h, *W2l, *Wfh, *Wfl;
    cudaGetSymbolAddress((void**)&h0,  g_h0);
    cudaGetSymbolAddress((void**)&h0h, g_h0h);
    cudaGetSymbolAddress((void**)&h0l, g_h0l);
    cudaGetSymbolAddress((void**)&h1h, g_h1h);
    cudaGetSymbolAddress((void**)&h1l, g_h1l);
    cudaGetSymbolAddress((void**)&h2h, g_h2h);
    cudaGetSymbolAddress((void**)&h2l, g_h2l);
    cudaGetSymbolAddress((void**)&h3,  g_h3);
    cudaGetSymbolAddress((void**)&W1h, g_W1h);
    cudaGetSymbolAddress((void**)&W1l, g_W1l);
    cudaGetSymbolAddress((void**)&W2h, g_W2h);
    cudaGetSymbolAddress((void**)&W2l, g_W2l);
    cudaGetSymbolAddress((void**)&Wfh, g_Wfh);
    cudaGetSymbolAddress((void**)&Wfl, g_Wfl);

    // allow 59.4 KB dynamic smem on the three gemm instantiations
    cudaFuncSetAttribute(k_gemm2<true , true >, cudaFuncAttributeMaxDynamicSharedMemorySize, SMEM_BYTES);
    cudaFuncSetAttribute(k_gemm2<false, true >, cudaFuncAttributeMaxDynamicSharedMemorySize, SMEM_BYTES);
    cudaFuncSetAttribute(k_gemm2<true , false>, cudaFuncAttributeMaxDynamicSharedMemorySize, SMEM_BYTES);

    k_detect<<<1, 1>>>(ei);
    k_convert<<<(N_EDGES + 255) / 256, 256>>>(ei);

    { int tot = N_PAD * IN_C / 4; k_init<<<(tot + 255) / 256, 256>>>(z); }
    k_scatter<<<N_EDGES / 8, 256>>>(z);

    // weight splits (tiny)
    k_split<<<(IN_C * HID / 4 + 255) / 256, 256>>>(W1,  W1h, W1l, IN_C * HID / 4);
    k_split<<<(HID * HID / 4 + 255) / 256, 256>>>(W2,  W2h, W2l, HID * HID / 4);
    k_split<<<(HID * FC1 / 4 + 255) / 256, 256>>>(Wf1, Wfh, Wfl, HID * FC1 / 4);
    // h0 split
    k_split<<<(N_PAD * IN_C / 4 + 255) / 256, 256>>>(h0, h0h, h0l, N_PAD * IN_C / 4);

    // h1 = selu(h0 @ W1 + b1)   -> split planes
    k_gemm2<true , true ><<<dim3(HID / 64, N_PAD / 128), 256, SMEM_BYTES>>>(
        h0h, h0l, W1h, W1l, b1, nullptr, h1h, h1l, HID, IN_C);
    // h2 = h1 @ W2 + b2         -> split planes
    k_gemm2<false, true ><<<dim3(HID / 64, N_PAD / 128), 256, SMEM_BYTES>>>(
        h1h, h1l, W2h, W2l, b2, nullptr, h2h, h2l, HID, HID);
    // h3 = selu(h2 @ Wf1 + bf1) -> fp32
    k_gemm2<true , false><<<dim3(FC1 / 64, N_PAD / 128), 256, SMEM_BYTES>>>(
        h2h, h2l, Wfh, Wfl, bf1, h3, nullptr, nullptr, FC1, HID);

    k_out<<<(N_NODES * 32 + 255) / 256, 256>>>(Wf2, bf2, out);
}